// round 9
// baseline (speedup 1.0000x reference)
#include <cuda_runtime.h>

#define NN 8192
#define EE 16384
#define EE4 (EE / 4)

// u = e .* (Ro^T a) in g_uv[0..EE), v = e .* (Ri^T b) in g_uv[EE..2EE).
__device__ float g_uv[2 * EE];
__device__ unsigned int g_ticket;   // phase2 tile dispatcher

// ---------------- Phase 1: column reductions (UNCHANGED from R8) -----------
// u[e] = ev[e] * sum_n Ro[n,e]*a[n],  v[e] = ev[e] * sum_n Ri[n,e]*b[n]
#define P1_CHUNK 128
#define P1_NCHUNK (NN / P1_CHUNK)      // 64
#define P1_KEEP 8
__global__ __launch_bounds__(256) void phase1(
    const float4* __restrict__ X4, const float* __restrict__ ker,
    const float* __restrict__ Ri, const float* __restrict__ Ro,
    const float* __restrict__ ev)
{
    __shared__ float sa[P1_CHUNK], sb[P1_CHUNK];
    int tid = threadIdx.x;
    int e   = blockIdx.x * 256 + tid;
    int yc  = blockIdx.y;
    int n0  = (P1_NCHUNK - 1 - yc) * P1_CHUNK;   // reversed row mapping

    if (tid < P1_CHUNK) {
        float4 x = X4[n0 + tid];
        sa[tid] = x.x * ker[0] + x.y * ker[1] + x.z * ker[2] + x.w * ker[3];
        sb[tid] = x.x * ker[4] + x.y * ker[5] + x.z * ker[6] + x.w * ker[7];
    }
    __syncthreads();

    const float* ro = Ro + (size_t)n0 * EE + e;
    const float* ri = Ri + (size_t)n0 * EE + e;
    float so = 0.0f, si = 0.0f;

    if (yc >= P1_NCHUNK - P1_KEEP) {
#pragma unroll 8
        for (int j = 0; j < P1_CHUNK; j++) {
            so += ro[(size_t)j * EE] * sa[j];
            si += ri[(size_t)j * EE] * sb[j];
        }
    } else {
#pragma unroll 8
        for (int j = 0; j < P1_CHUNK; j++) {
            so += __ldcs(ro + (size_t)j * EE) * sa[j];
            si += __ldcs(ri + (size_t)j * EE) * sb[j];
        }
    }
    float w = ev[e];
    atomicAdd(&g_uv[e],      w * so);
    atomicAdd(&g_uv[EE + e], w * si);
}

// ---------------- Phase 2: row reductions (persistent, higher occupancy) ---
// out[n] = sum_e Ri[n,e]*u[e] + Ro[n,e]*v[e] + X[n].k2
// __launch_bounds__(256,5): cap regs ~51 -> 5 blocks/SM (40 warps) for more
// loads in flight. r-loop split into pairs to shorten float4 live ranges.
#define RPB 4
#define NTILES (NN / RPB)              // 2048
#define P2_BLOCKS (148 * 5)
__global__ __launch_bounds__(256, 5) void phase2(
    const float4* __restrict__ X4, const float* __restrict__ ker,
    const float4* __restrict__ Ri4, const float4* __restrict__ Ro4,
    float* __restrict__ out)
{
    __shared__ float red[RPB][256];
    __shared__ int sTile;
    int tid = threadIdx.x;

    const float4* u4 = (const float4*)g_uv;
    const float4* v4 = u4 + EE4;

    for (;;) {
        if (tid == 0) sTile = (int)atomicAdd(&g_ticket, 1u);
        __syncthreads();
        int tile = sTile;
        if (tile >= NTILES) break;
        int n0 = tile * RPB;

        float s[RPB];
#pragma unroll
        for (int r = 0; r < RPB; r++) s[r] = 0.0f;

#pragma unroll 4
        for (int it = 0; it < EE4 / 256; it++) {
            int e4 = it * 256 + tid;
            // Pair 0: rows n0, n0+1
            {
                float4 u = u4[e4];
                float4 v = v4[e4];
                float4 a0 = __ldcs(Ri4 + (size_t)(n0 + 0) * EE4 + e4);
                float4 b0 = __ldcs(Ro4 + (size_t)(n0 + 0) * EE4 + e4);
                float4 a1 = __ldcs(Ri4 + (size_t)(n0 + 1) * EE4 + e4);
                float4 b1 = __ldcs(Ro4 + (size_t)(n0 + 1) * EE4 + e4);
                s[0] += a0.x * u.x + a0.y * u.y + a0.z * u.z + a0.w * u.w
                      + b0.x * v.x + b0.y * v.y + b0.z * v.z + b0.w * v.w;
                s[1] += a1.x * u.x + a1.y * u.y + a1.z * u.z + a1.w * u.w
                      + b1.x * v.x + b1.y * v.y + b1.z * v.z + b1.w * v.w;
            }
            // Pair 1: rows n0+2, n0+3 (u/v reload: L1/L2 hit, frees regs)
            {
                float4 u = u4[e4];
                float4 v = v4[e4];
                float4 a2 = __ldcs(Ri4 + (size_t)(n0 + 2) * EE4 + e4);
                float4 b2 = __ldcs(Ro4 + (size_t)(n0 + 2) * EE4 + e4);
                float4 a3 = __ldcs(Ri4 + (size_t)(n0 + 3) * EE4 + e4);
                float4 b3 = __ldcs(Ro4 + (size_t)(n0 + 3) * EE4 + e4);
                s[2] += a2.x * u.x + a2.y * u.y + a2.z * u.z + a2.w * u.w
                      + b2.x * v.x + b2.y * v.y + b2.z * v.z + b2.w * v.w;
                s[3] += a3.x * u.x + a3.y * u.y + a3.z * u.z + a3.w * u.w
                      + b3.x * v.x + b3.y * v.y + b3.z * v.z + b3.w * v.w;
            }
        }

#pragma unroll
        for (int r = 0; r < RPB; r++) red[r][tid] = s[r];
        __syncthreads();
        for (int st = 128; st > 0; st >>= 1) {
            if (tid < st) {
#pragma unroll
                for (int r = 0; r < RPB; r++) red[r][tid] += red[r][tid + st];
            }
            __syncthreads();
        }
        if (tid < RPB) {
            float4 x = X4[n0 + tid];
            out[n0 + tid] = red[tid][0]
                          + x.x * ker[8] + x.y * ker[9] + x.z * ker[10] + x.w * ker[11];
        }
        __syncthreads();
    }
}

extern "C" void kernel_launch(void* const* d_in, const int* in_sizes, int n_in,
                              void* d_out, int out_size) {
    const float4* X4  = (const float4*)d_in[0];
    const float*  ev  = (const float*)d_in[1];
    const float*  Ri  = (const float*)d_in[2];
    const float*  Ro  = (const float*)d_in[3];
    const float*  ker = (const float*)d_in[4];
    float* out = (float*)d_out;

    void* uvptr = nullptr;
    cudaGetSymbolAddress(&uvptr, g_uv);
    cudaMemsetAsync(uvptr, 0, 2 * EE * sizeof(float));
    void* tkptr = nullptr;
    cudaGetSymbolAddress(&tkptr, g_ticket);
    cudaMemsetAsync(tkptr, 0, sizeof(unsigned int));

    dim3 g1(EE / 256, P1_NCHUNK);                  // (64, 64)
    phase1<<<g1, 256>>>(X4, ker, Ri, Ro, ev);

    phase2<<<P2_BLOCKS, 256>>>(X4, ker,
                               (const float4*)Ri, (const float4*)Ro, out);
}